// round 2
// baseline (speedup 1.0000x reference)
#include <cuda_runtime.h>
#include <cuda_bf16.h>

#define GSZ 8
#define DIMN 160
#define N3 (DIMN*DIMN*DIMN)

__device__ __forceinline__ float reflectf(float c) {
    // mirror about edge samples, period 2*(n-1) = 318, n-1 = 159
    c = fabsf(c);
    c = fmodf(c, 318.0f);
    if (c > 159.0f) c = 318.0f - c;
    return c;
}

__global__ void __launch_bounds__(256) elastic_kernel(
    const float* __restrict__ x,       // [B,2,160,160,160]
    const float* __restrict__ flow,    // [B,3,8,8,8]
    float* __restrict__ out)           // [B,2,160,160,160]
{
    __shared__ float sf[3 * GSZ * GSZ * GSZ];   // 6 KB coarse flow for this batch

    const int b = blockIdx.y;
    const float* fb = flow + (size_t)b * 3 * GSZ * GSZ * GSZ;
    for (int i = threadIdx.x; i < 3 * GSZ * GSZ * GSZ; i += blockDim.x)
        sf[i] = fb[i];
    __syncthreads();

    const int spatial = blockIdx.x * blockDim.x + threadIdx.x;  // 0 .. 160^3-1 exactly
    const int w = spatial % DIMN;
    const int t = spatial / DIMN;
    const int h = t % DIMN;
    const int d = t / DIMN;

    // ---- coarse flow upsample (trilinear, align_corners, clamp) ----
    const float s = 7.0f / 159.0f;
    const float cz = d * s, cy = h * s, cx = w * s;
    int iz0 = (int)cz, iy0 = (int)cy, ix0 = (int)cx;
    const float fz = cz - iz0, fy = cy - iy0, fx = cx - ix0;
    const int iz1 = min(iz0 + 1, GSZ - 1);
    const int iy1 = min(iy0 + 1, GSZ - 1);
    const int ix1 = min(ix0 + 1, GSZ - 1);

    const float gz0 = 1.0f - fz, gy0 = 1.0f - fy, gx0 = 1.0f - fx;
    float cw[8];
    cw[0] = gz0 * gy0 * gx0;  cw[1] = gz0 * gy0 * fx;
    cw[2] = gz0 * fy  * gx0;  cw[3] = gz0 * fy  * fx;
    cw[4] = fz  * gy0 * gx0;  cw[5] = fz  * gy0 * fx;
    cw[6] = fz  * fy  * gx0;  cw[7] = fz  * fy  * fx;

    int ci[8];
    ci[0] = (iz0 * GSZ + iy0) * GSZ + ix0;
    ci[1] = (iz0 * GSZ + iy0) * GSZ + ix1;
    ci[2] = (iz0 * GSZ + iy1) * GSZ + ix0;
    ci[3] = (iz0 * GSZ + iy1) * GSZ + ix1;
    ci[4] = (iz1 * GSZ + iy0) * GSZ + ix0;
    ci[5] = (iz1 * GSZ + iy0) * GSZ + ix1;
    ci[6] = (iz1 * GSZ + iy1) * GSZ + ix0;
    ci[7] = (iz1 * GSZ + iy1) * GSZ + ix1;

    float upx = 0.f, upy = 0.f, upz = 0.f;
    #pragma unroll
    for (int k = 0; k < 8; k++) {
        upx = fmaf(cw[k], sf[ci[k]],             upx);
        upy = fmaf(cw[k], sf[512 + ci[k]],       upy);
        upz = fmaf(cw[k], sf[1024 + ci[k]],      upz);
    }

    // ---- warp coordinate: i = voxel + up * (n-1)/2 ; mirror-reflect ----
    float px = reflectf((float)w + upx * 79.5f);
    float py = reflectf((float)h + upy * 79.5f);
    float pz = reflectf((float)d + upz * 79.5f);

    int jx0 = (int)px, jy0 = (int)py, jz0 = (int)pz;
    jx0 = min(jx0, DIMN - 1); jy0 = min(jy0, DIMN - 1); jz0 = min(jz0, DIMN - 1);
    const float ax = px - jx0, ay = py - jy0, az = pz - jz0;
    const int jx1 = min(jx0 + 1, DIMN - 1);
    const int jy1 = min(jy0 + 1, DIMN - 1);
    const int jz1 = min(jz0 + 1, DIMN - 1);

    const float bx0 = 1.0f - ax, by0 = 1.0f - ay, bz0 = 1.0f - az;
    float tw[8];
    tw[0] = bz0 * by0 * bx0;  tw[1] = bz0 * by0 * ax;
    tw[2] = bz0 * ay  * bx0;  tw[3] = bz0 * ay  * ax;
    tw[4] = az  * by0 * bx0;  tw[5] = az  * by0 * ax;
    tw[6] = az  * ay  * bx0;  tw[7] = az  * ay  * ax;

    int off[8];
    const int r00 = (jz0 * DIMN + jy0) * DIMN;
    const int r01 = (jz0 * DIMN + jy1) * DIMN;
    const int r10 = (jz1 * DIMN + jy0) * DIMN;
    const int r11 = (jz1 * DIMN + jy1) * DIMN;
    off[0] = r00 + jx0;  off[1] = r00 + jx1;
    off[2] = r01 + jx0;  off[3] = r01 + jx1;
    off[4] = r10 + jx0;  off[5] = r10 + jx1;
    off[6] = r11 + jx0;  off[7] = r11 + jx1;

    const float* __restrict__ x0 = x + (size_t)b * 2 * N3;       // channel 0
    const float* __restrict__ x1 = x0 + N3;                      // channel 1

    float v0 = 0.f, v1 = 0.f;
    #pragma unroll
    for (int k = 0; k < 8; k++) {
        v0 = fmaf(tw[k], __ldg(x0 + off[k]), v0);
        v1 = fmaf(tw[k], __ldg(x1 + off[k]), v1);
    }

    float* __restrict__ o0 = out + (size_t)b * 2 * N3;
    o0[spatial]      = v0;
    o0[N3 + spatial] = v1;
}

extern "C" void kernel_launch(void* const* d_in, const int* in_sizes, int n_in,
                              void* d_out, int out_size) {
    const float* x    = (const float*)d_in[0];
    const float* flow = (const float*)d_in[1];
    float* out        = (float*)d_out;

    dim3 block(256);
    dim3 grid(N3 / 256, 4);   // 160^3 = 4,096,000 divisible by 256 -> 16000 blocks per batch
    elastic_kernel<<<grid, block>>>(x, flow, out);
}